// round 4
// baseline (speedup 1.0000x reference)
#include <cuda_runtime.h>
#include <cstdint>

#define NMAX 50000
#define RK 300
#define GRID 148

__device__ float g_h[NMAX * 64];
__device__ float g_agg[NMAX * 64];
__device__ float2 g_fw1frag[5 * 8 * 8 * 32];  // [c][s][t][lane] -> (b0,b1), tf32-rounded
__device__ float2 g_fw2frag[8 * 8 * 32];      // [s][t][lane]
__device__ int g_is64;

__device__ __forceinline__ float sspf(float x) {
    float t = __expf(-fabsf(x));
    return fmaxf(x, 0.f) + __logf(1.f + t) - 0.69314718055994531f;
}
__device__ __forceinline__ uint32_t cvt_tf32(float x) {
    uint32_t r; asm("cvt.rna.tf32.f32 %0, %1;" : "=r"(r) : "f"(x)); return r;
}
__device__ __forceinline__ float tf32r(float x) { return __uint_as_float(cvt_tf32(x)); }

__device__ __forceinline__ void mma_tf32(float d[4], uint32_t a0, uint32_t a1,
                                         uint32_t a2, uint32_t a3,
                                         uint32_t b0, uint32_t b1) {
    asm volatile(
        "mma.sync.aligned.m16n8k8.row.col.f32.tf32.tf32.f32 "
        "{%0,%1,%2,%3}, {%4,%5,%6,%7}, {%8,%9}, {%0,%1,%2,%3};"
        : "+f"(d[0]), "+f"(d[1]), "+f"(d[2]), "+f"(d[3])
        : "r"(a0), "r"(a1), "r"(a2), "r"(a3), "r"(b0), "r"(b1));
}
__device__ __forceinline__ void cp16(uint32_t saddr, const void* g, int sz) {
    asm volatile("cp.async.cg.shared.global [%0], [%1], 16, %2;"
                 :: "r"(saddr), "l"(g), "r"(sz));
}
__device__ __forceinline__ void cp_commit() { asm volatile("cp.async.commit_group;"); }
__device__ __forceinline__ void cp_wait0()  { asm volatile("cp.async.wait_group 0;"); }

__device__ __forceinline__ void bulk_g2s(uint32_t dst, const void* src, int bytes,
                                         uint32_t mbar) {
    asm volatile(
        "cp.async.bulk.shared::cta.global.mbarrier::complete_tx::bytes [%0], [%1], %2, [%3];"
        :: "r"(dst), "l"(src), "r"(bytes), "r"(mbar) : "memory");
}
__device__ __forceinline__ void mbar_init(uint32_t a, uint32_t cnt) {
    asm volatile("mbarrier.init.shared.b64 [%0], %1;" :: "r"(a), "r"(cnt) : "memory");
}
__device__ __forceinline__ void mbar_expect(uint32_t a, uint32_t tx) {
    asm volatile("mbarrier.arrive.expect_tx.shared.b64 _, [%0], %1;"
                 :: "r"(a), "r"(tx) : "memory");
}
__device__ __forceinline__ void mbar_wait(uint32_t a, uint32_t ph) {
    uint32_t done = 0;
    do {
        asm volatile(
            "{\n\t.reg .pred p;\n\t"
            "mbarrier.try_wait.parity.acquire.cta.shared::cta.b64 p, [%1], %2, 0x989680;\n\t"
            "selp.b32 %0, 1, 0, p;\n\t}"
            : "=r"(done) : "r"(a), "r"(ph) : "memory");
    } while (!done);
}

__global__ void detect_idx_kernel(const int* __restrict__ ei32) {
    if (threadIdx.x == 0 && blockIdx.x == 0) {
        int ornz = 0;
#pragma unroll
        for (int i = 0; i < 64; ++i) ornz |= ei32[2 * i + 1];
        g_is64 = (ornz == 0) ? 1 : 0;
    }
}

// fragment-major tf32 weights: k = c*64 + 8s + t4 (+4 for b1), n = 8t + g4
__global__ void prep_frag_kernel(const float* __restrict__ fw1,
                                 const float* __restrict__ fw2) {
    int i = blockIdx.x * blockDim.x + threadIdx.x;
    if (i < 5 * 8 * 8 * 32) {
        int lane = i & 31, t = (i >> 5) & 7, s = (i >> 8) & 7, c = i >> 11;
        int t4 = lane & 3, g4 = lane >> 2;
        int k = c * 64 + 8 * s + t4, n = 8 * t + g4;
        float b0 = (k < RK) ? tf32r(fw1[k * 64 + n]) : 0.f;
        float b1 = (k + 4 < RK) ? tf32r(fw1[(k + 4) * 64 + n]) : 0.f;
        g_fw1frag[i] = make_float2(b0, b1);
    }
    if (i < 8 * 8 * 32) {
        int lane = i & 31, t = (i >> 5) & 7, s = i >> 8;
        int t4 = lane & 3, g4 = lane >> 2;
        int k = 8 * s + t4, n = 8 * t + g4;
        g_fw2frag[i] = make_float2(tf32r(fw2[k * 64 + n]), tf32r(fw2[(k + 4) * 64 + n]));
    }
}

__global__ void zero_agg_kernel(int total4) {
    int i = blockIdx.x * blockDim.x + threadIdx.x;
    if (i < total4) ((float4*)g_agg)[i] = make_float4(0.f, 0.f, 0.f, 0.f);
}

// ---------------------------------------------------------------------------
// node kernels (unchanged from passing version)
// ---------------------------------------------------------------------------
__global__ void node_pre_kernel(const float* __restrict__ x, const float* __restrict__ W,
                                const float* __restrict__ b, int N) {
    __shared__ float Ws[64 * 65]; __shared__ float bs[64]; __shared__ float xs[4][68];
    int tid = threadIdx.x;
    for (int i = tid; i < 4096; i += 256) Ws[(i >> 6) * 65 + (i & 63)] = W[i];
    if (tid < 64) bs[tid] = b[tid];
    int j = tid & 63, g = tid >> 6;
    int n0 = blockIdx.x * 64;
    for (int it = 0; it < 16; ++it) {
        int node = n0 + it * 4 + g;
        __syncthreads();
        xs[g][j] = (node < N) ? x[(long)node * 64 + j] : 0.f;
        __syncthreads();
        float acc = bs[j];
#pragma unroll
        for (int k = 0; k < 64; k += 4) {
            float4 xv = *(const float4*)&xs[g][k];
            acc += xv.x * Ws[(k + 0) * 65 + j];
            acc += xv.y * Ws[(k + 1) * 65 + j];
            acc += xv.z * Ws[(k + 2) * 65 + j];
            acc += xv.w * Ws[(k + 3) * 65 + j];
        }
        if (node < N) g_h[(long)node * 64 + j] = acc;
    }
}

__global__ void node_post_kernel(const float* __restrict__ x0, const float* __restrict__ W2,
                                 const float* __restrict__ b2, const float* __restrict__ W3,
                                 const float* __restrict__ b3, float* __restrict__ out, int N) {
    __shared__ float W2s[64 * 65], W3s[64 * 65];
    __shared__ float b2s[64], b3s[64];
    __shared__ float xs[4][68], ts[4][68];
    int tid = threadIdx.x;
    for (int i = tid; i < 4096; i += 256) {
        W2s[(i >> 6) * 65 + (i & 63)] = W2[i];
        W3s[(i >> 6) * 65 + (i & 63)] = W3[i];
    }
    if (tid < 64) { b2s[tid] = b2[tid]; b3s[tid] = b3[tid]; }
    int j = tid & 63, g = tid >> 6;
    int n0 = blockIdx.x * 64;
    for (int it = 0; it < 16; ++it) {
        int node = n0 + it * 4 + g;
        __syncthreads();
        xs[g][j] = (node < N) ? g_agg[(long)node * 64 + j] : 0.f;
        __syncthreads();
        float acc = b2s[j];
#pragma unroll
        for (int k = 0; k < 64; k += 4) {
            float4 xv = *(const float4*)&xs[g][k];
            acc += xv.x * W2s[(k + 0) * 65 + j];
            acc += xv.y * W2s[(k + 1) * 65 + j];
            acc += xv.z * W2s[(k + 2) * 65 + j];
            acc += xv.w * W2s[(k + 3) * 65 + j];
        }
        ts[g][j] = sspf(acc);
        __syncthreads();
        float acc2 = b3s[j];
#pragma unroll
        for (int k = 0; k < 64; k += 4) {
            float4 tv = *(const float4*)&ts[g][k];
            acc2 += tv.x * W3s[(k + 0) * 65 + j];
            acc2 += tv.y * W3s[(k + 1) * 65 + j];
            acc2 += tv.z * W3s[(k + 2) * 65 + j];
            acc2 += tv.w * W3s[(k + 3) * 65 + j];
        }
        if (node < N) out[(long)node * 64 + j] = acc2 + x0[(long)node * 64 + j];
    }
}

// ---------------------------------------------------------------------------
// edge kernel: persistent CTAs, bulk-async rbf, resident fragment weights
// smem layout (floats):
#define OFF_A   0            // 2 x 128 x 68 = 17408
#define OFF_FW1 17408        // 10240 float2 = 20480 floats
#define OFF_FW2 37888        // 2048 float2  = 4096 floats
#define OFF_C   41984        // 128 x 68     = 8704
#define OFF_B1  50688
#define OFF_B2  50752
#define OFF_MB  50816        // 2 mbarriers (8B each)
#define SMEM_FLOATS 50824

__global__ void __launch_bounds__(256, 1)
edge_kernel(const void* __restrict__ ei, const float* __restrict__ rbf,
            const float* __restrict__ dist, const float* __restrict__ cutoff,
            const float* __restrict__ fb1, const float* __restrict__ fb2,
            int E, int NT) {
    extern __shared__ float sm[];
    uint32_t sbase = (uint32_t)__cvta_generic_to_shared(sm);
    int tid = threadIdx.x, lane = tid & 31, warp = tid >> 5;
    int t4 = lane & 3, g4 = lane >> 2, rw = warp * 16;
    const float2* FW1 = (const float2*)(sm + OFF_FW1);
    const float2* FW2 = (const float2*)(sm + OFF_FW2);
    uint32_t mb0 = sbase + OFF_MB * 4, mb1 = mb0 + 8;

    // zero A buffers (NaN-proofing for K-tail / short tiles), stage weights+biases
    for (int i = tid; i < 17408; i += 256) sm[OFF_A + i] = 0.f;
    for (int i = tid; i < 5120; i += 256)
        cp16(sbase + (OFF_FW1 + i * 4) * 4, (const char*)g_fw1frag + i * 16, 16);
    for (int i = tid; i < 1024; i += 256)
        cp16(sbase + (OFF_FW2 + i * 4) * 4, (const char*)g_fw2frag + i * 16, 16);
    cp_commit();
    if (tid < 64) { sm[OFF_B1 + tid] = fb1[tid]; sm[OFF_B2 + tid] = fb2[tid]; }
    if (tid == 0) { mbar_init(mb0, 1); mbar_init(mb1, 1); }
    cp_wait0();
    asm volatile("fence.proxy.async.shared::cta;" ::: "memory");
    __syncthreads();

    // warp-0 issues chunk loads: one 256B (176B for c=4) bulk per edge row
    auto issue = [&](long t, int c, int b) {
        if (t >= (long)NT || warp != 0) return;
        long e0 = t * 128;
        int V = (int)((long)E - e0 < 128 ? (long)E - e0 : 128);
        int csz = (c == 4) ? 176 : 256;
        if (lane == 0) mbar_expect(b ? mb1 : mb0, (uint32_t)(V * csz));
#pragma unroll
        for (int i = 0; i < 4; ++i) {
            int r = lane + 32 * i;
            if (r < V)
                bulk_g2s(sbase + (OFF_A + b * 8704 + r * 68) * 4,
                         rbf + (e0 + r) * (long)RK + c * 64, csz, b ? mb1 : mb0);
        }
    };

    long tile = blockIdx.x;
    issue(tile, 0, 0);
    issue(tile, 1, 1);
    int ph0 = 0, ph1 = 0;

    for (; tile < (long)NT; tile += GRID) {
        long e0 = tile * 128;
        float acc[8][4];
#pragma unroll
        for (int t = 0; t < 8; ++t)
#pragma unroll
            for (int j = 0; j < 4; ++j) acc[t][j] = 0.f;

        // GEMM1: 5 chunks of K=64
#pragma unroll 1
        for (int c = 0; c < 5; ++c) {
            int b = c & 1;
            if (b) { mbar_wait(mb1, ph1); ph1 ^= 1; }
            else   { mbar_wait(mb0, ph0); ph0 ^= 1; }
            const float* A = sm + OFF_A + b * 8704;
#pragma unroll
            for (int s = 0; s < 8; ++s) {
                int col = 8 * s + t4;
                uint32_t a0 = cvt_tf32(A[(rw + g4) * 68 + col]);
                uint32_t a1 = cvt_tf32(A[(rw + g4 + 8) * 68 + col]);
                uint32_t a2 = cvt_tf32(A[(rw + g4) * 68 + col + 4]);
                uint32_t a3 = cvt_tf32(A[(rw + g4 + 8) * 68 + col + 4]);
#pragma unroll
                for (int t = 0; t < 8; ++t) {
                    float2 bb = FW1[((c * 8 + s) * 8 + t) * 32 + lane];
                    mma_tf32(acc[t], a0, a1, a2, a3,
                             __float_as_uint(bb.x), __float_as_uint(bb.y));
                }
            }
            __syncthreads();
            if (c == 0) issue(tile, 2, 0);
            else if (c == 1) issue(tile, 3, 1);
            else if (c == 2) issue(tile, 4, 0);
            else if (c == 3) issue(tile + GRID, 1, 1);
            else issue(tile + GRID, 0, 0);
        }

        // bias + ssp -> C1 (own-warp rows)
#pragma unroll
        for (int t = 0; t < 8; ++t) {
            int cb = 8 * t + 2 * t4;
            float b0v = sm[OFF_B1 + cb], b1v = sm[OFF_B1 + cb + 1];
            *(float2*)&sm[OFF_C + (rw + g4) * 68 + cb] =
                make_float2(sspf(acc[t][0] + b0v), sspf(acc[t][1] + b1v));
            *(float2*)&sm[OFF_C + (rw + g4 + 8) * 68 + cb] =
                make_float2(sspf(acc[t][2] + b0v), sspf(acc[t][3] + b1v));
        }
        __syncwarp();

        // GEMM2
        float acc2[8][4];
#pragma unroll
        for (int t = 0; t < 8; ++t)
#pragma unroll
            for (int j = 0; j < 4; ++j) acc2[t][j] = 0.f;
#pragma unroll
        for (int s = 0; s < 8; ++s) {
            int col = 8 * s + t4;
            uint32_t a0 = cvt_tf32(sm[OFF_C + (rw + g4) * 68 + col]);
            uint32_t a1 = cvt_tf32(sm[OFF_C + (rw + g4 + 8) * 68 + col]);
            uint32_t a2 = cvt_tf32(sm[OFF_C + (rw + g4) * 68 + col + 4]);
            uint32_t a3 = cvt_tf32(sm[OFF_C + (rw + g4 + 8) * 68 + col + 4]);
#pragma unroll
            for (int t = 0; t < 8; ++t) {
                float2 bb = FW2[(s * 8 + t) * 32 + lane];
                mma_tf32(acc2[t], a0, a1, a2, a3,
                         __float_as_uint(bb.x), __float_as_uint(bb.y));
            }
        }
        __syncwarp();
#pragma unroll
        for (int t = 0; t < 8; ++t) {
            int cb = 8 * t + 2 * t4;
            float b0v = sm[OFF_B2 + cb], b1v = sm[OFF_B2 + cb + 1];
            *(float2*)&sm[OFF_C + (rw + g4) * 68 + cb] =
                make_float2(sspf(acc2[t][0] + b0v), sspf(acc2[t][1] + b1v));
            *(float2*)&sm[OFF_C + (rw + g4 + 8) * 68 + cb] =
                make_float2(sspf(acc2[t][2] + b0v), sspf(acc2[t][3] + b1v));
        }
        __syncthreads();

        // epilogue: gather h[src], scatter atomics into agg[dst]
        int el = tid >> 1, half = tid & 1;
        long e = e0 + el;
        if (e < (long)E) {
            long long dstn, srcn;
            if (g_is64) {
                const long long* p = (const long long*)ei;
                dstn = p[e]; srcn = p[(long)E + e];
            } else {
                const int* p = (const int*)ei;
                dstn = p[e]; srcn = p[(long)E + e];
            }
            dstn = dstn < 0 ? 0 : (dstn >= NMAX ? NMAX - 1 : dstn);
            srcn = srcn < 0 ? 0 : (srcn >= NMAX ? NMAX - 1 : srcn);
            float f = 1.f + __cosf(3.14159265f * dist[e] / *cutoff);
            const float* hrow = g_h + (long)srcn * 64 + half * 32;
            float* arow = g_agg + (long)dstn * 64 + half * 32;
            const float* wrow = sm + OFF_C + el * 68 + half * 32;
#pragma unroll
            for (int j = 0; j < 8; ++j) {
                float4 w = *(const float4*)(wrow + 4 * j);
                float4 h4 = *(const float4*)(hrow + 4 * j);
                atomicAdd((float4*)(arow + 4 * j),
                          make_float4(w.x * h4.x * f, w.y * h4.y * f,
                                      w.z * h4.z * f, w.w * h4.w * f));
            }
        }
        __syncthreads();
    }
}

// ---------------------------------------------------------------------------
extern "C" void kernel_launch(void* const* d_in, const int* in_sizes, int n_in,
                              void* d_out, int out_size) {
    const void* ei       = d_in[0];
    const float* x       = (const float*)d_in[1];
    const float* rbf     = (const float*)d_in[2];
    const float* dist    = (const float*)d_in[3];
    const float* cutoff  = (const float*)d_in[4];
    const float* fw1     = (const float*)d_in[5];
    const float* fb1     = (const float*)d_in[6];
    const float* fw2     = (const float*)d_in[7];
    const float* fb2     = (const float*)d_in[8];
    const float* l1w     = (const float*)d_in[9];
    const float* l1b     = (const float*)d_in[10];
    const float* l2w     = (const float*)d_in[11];
    const float* l2b     = (const float*)d_in[12];
    const float* l3w     = (const float*)d_in[13];
    const float* l3b     = (const float*)d_in[14];

    int E = in_sizes[0] / 2;
    int N = in_sizes[1] / 64;
    int NT = (E + 127) / 128;

    cudaFuncSetAttribute(edge_kernel, cudaFuncAttributeMaxDynamicSharedMemorySize,
                         SMEM_FLOATS * 4);

    detect_idx_kernel<<<1, 32>>>((const int*)ei);
    prep_frag_kernel<<<(5 * 8 * 8 * 32 + 255) / 256, 256>>>(fw1, fw2);
    zero_agg_kernel<<<(N * 16 + 255) / 256, 256>>>(N * 16);
    node_pre_kernel<<<(N + 63) / 64, 256>>>(x, l1w, l1b, N);
    edge_kernel<<<GRID, 256, SMEM_FLOATS * 4>>>(ei, rbf, dist, cutoff, fb1, fb2, E, NT);
    node_post_kernel<<<(N + 63) / 64, 256>>>(x, l2w, l2b, l3w, l3b, (float*)d_out, N);
}

// round 5
// speedup vs baseline: 2.1568x; 2.1568x over previous
#include <cuda_runtime.h>
#include <cuda.h>
#include <cstdint>

#define NMAX 50000
#define RK 300
#define TILE 256

__device__ float g_h[NMAX * 64];
__device__ float g_agg[NMAX * 64];
__device__ float2 g_fw1frag[10 * 4 * 8 * 32];  // [c][s][t][lane] -> (b0,b1)
__device__ float2 g_fw2frag[8 * 8 * 32];       // [s][t][lane]
__device__ int g_is64;

__device__ __forceinline__ float sspf(float x) {
    float t = __expf(-fabsf(x));
    return fmaxf(x, 0.f) + __logf(1.f + t) - 0.69314718055994531f;
}
__device__ __forceinline__ uint32_t cvt_tf32(float x) {
    uint32_t r; asm("cvt.rna.tf32.f32 %0, %1;" : "=r"(r) : "f"(x)); return r;
}
__device__ __forceinline__ float tf32r(float x) { return __uint_as_float(cvt_tf32(x)); }

__device__ __forceinline__ void mma_tf32(float d[4], uint32_t a0, uint32_t a1,
                                         uint32_t a2, uint32_t a3,
                                         uint32_t b0, uint32_t b1) {
    asm volatile(
        "mma.sync.aligned.m16n8k8.row.col.f32.tf32.tf32.f32 "
        "{%0,%1,%2,%3}, {%4,%5,%6,%7}, {%8,%9}, {%0,%1,%2,%3};"
        : "+f"(d[0]), "+f"(d[1]), "+f"(d[2]), "+f"(d[3])
        : "r"(a0), "r"(a1), "r"(a2), "r"(a3), "r"(b0), "r"(b1));
}
__device__ __forceinline__ void cp16(uint32_t saddr, const void* g, int sz) {
    asm volatile("cp.async.cg.shared.global [%0], [%1], 16, %2;"
                 :: "r"(saddr), "l"(g), "r"(sz));
}
__device__ __forceinline__ void cp_commit() { asm volatile("cp.async.commit_group;"); }
__device__ __forceinline__ void cp_wait0()  { asm volatile("cp.async.wait_group 0;"); }

__device__ __forceinline__ void tma2d(uint32_t dst, const void* map, int x, int y,
                                      uint32_t mbar) {
    asm volatile(
        "cp.async.bulk.tensor.2d.shared::cta.global.tile.mbarrier::complete_tx::bytes "
        "[%0], [%1, {%2, %3}], [%4];"
        :: "r"(dst), "l"(map), "r"(x), "r"(y), "r"(mbar) : "memory");
}
__device__ __forceinline__ void mbar_init(uint32_t a, uint32_t cnt) {
    asm volatile("mbarrier.init.shared.b64 [%0], %1;" :: "r"(a), "r"(cnt) : "memory");
}
__device__ __forceinline__ void mbar_expect(uint32_t a, uint32_t tx) {
    asm volatile("mbarrier.arrive.expect_tx.shared.b64 _, [%0], %1;"
                 :: "r"(a), "r"(tx) : "memory");
}
__device__ __forceinline__ void mbar_wait(uint32_t a, uint32_t ph) {
    uint32_t done = 0;
    do {
        asm volatile(
            "{\n\t.reg .pred p;\n\t"
            "mbarrier.try_wait.parity.acquire.cta.shared::cta.b64 p, [%1], %2, 0x989680;\n\t"
            "selp.b32 %0, 1, 0, p;\n\t}"
            : "=r"(done) : "r"(a), "r"(ph) : "memory");
    } while (!done);
}

__global__ void detect_idx_kernel(const int* __restrict__ ei32) {
    if (threadIdx.x == 0 && blockIdx.x == 0) {
        int ornz = 0;
#pragma unroll
        for (int i = 0; i < 64; ++i) ornz |= ei32[2 * i + 1];
        g_is64 = (ornz == 0) ? 1 : 0;
    }
}

// fragment-major tf32 weights. fw1: k = c*32 + 8s + t4 (+4 for b1), n = 8t + g4
__global__ void prep_frag_kernel(const float* __restrict__ fw1,
                                 const float* __restrict__ fw2) {
    int i = blockIdx.x * blockDim.x + threadIdx.x;
    if (i < 10 * 4 * 8 * 32) {
        int lane = i & 31, t = (i >> 5) & 7, s = (i >> 8) & 3, c = i >> 10;
        int t4 = lane & 3, g4 = lane >> 2;
        int k = c * 32 + 8 * s + t4, n = 8 * t + g4;
        float b0 = (k < RK) ? tf32r(fw1[k * 64 + n]) : 0.f;
        float b1 = (k + 4 < RK) ? tf32r(fw1[(k + 4) * 64 + n]) : 0.f;
        g_fw1frag[i] = make_float2(b0, b1);
    }
    if (i < 8 * 8 * 32) {
        int lane = i & 31, t = (i >> 5) & 7, s = i >> 8;
        int t4 = lane & 3, g4 = lane >> 2;
        int k = 8 * s + t4, n = 8 * t + g4;
        g_fw2frag[i] = make_float2(tf32r(fw2[k * 64 + n]), tf32r(fw2[(k + 4) * 64 + n]));
    }
}

__global__ void zero_agg_kernel(int total4) {
    int i = blockIdx.x * blockDim.x + threadIdx.x;
    if (i < total4) ((float4*)g_agg)[i] = make_float4(0.f, 0.f, 0.f, 0.f);
}

// ---------------------------------------------------------------------------
// node kernels (proven)
// ---------------------------------------------------------------------------
__global__ void node_pre_kernel(const float* __restrict__ x, const float* __restrict__ W,
                                const float* __restrict__ b, int N) {
    __shared__ float Ws[64 * 65]; __shared__ float bs[64]; __shared__ float xs[4][68];
    int tid = threadIdx.x;
    for (int i = tid; i < 4096; i += 256) Ws[(i >> 6) * 65 + (i & 63)] = W[i];
    if (tid < 64) bs[tid] = b[tid];
    int j = tid & 63, g = tid >> 6;
    int n0 = blockIdx.x * 64;
    for (int it = 0; it < 16; ++it) {
        int node = n0 + it * 4 + g;
        __syncthreads();
        xs[g][j] = (node < N) ? x[(long)node * 64 + j] : 0.f;
        __syncthreads();
        float acc = bs[j];
#pragma unroll
        for (int k = 0; k < 64; k += 4) {
            float4 xv = *(const float4*)&xs[g][k];
            acc += xv.x * Ws[(k + 0) * 65 + j];
            acc += xv.y * Ws[(k + 1) * 65 + j];
            acc += xv.z * Ws[(k + 2) * 65 + j];
            acc += xv.w * Ws[(k + 3) * 65 + j];
        }
        if (node < N) g_h[(long)node * 64 + j] = acc;
    }
}

__global__ void node_post_kernel(const float* __restrict__ x0, const float* __restrict__ W2,
                                 const float* __restrict__ b2, const float* __restrict__ W3,
                                 const float* __restrict__ b3, float* __restrict__ out, int N) {
    __shared__ float W2s[64 * 65], W3s[64 * 65];
    __shared__ float b2s[64], b3s[64];
    __shared__ float xs[4][68], ts[4][68];
    int tid = threadIdx.x;
    for (int i = tid; i < 4096; i += 256) {
        W2s[(i >> 6) * 65 + (i & 63)] = W2[i];
        W3s[(i >> 6) * 65 + (i & 63)] = W3[i];
    }
    if (tid < 64) { b2s[tid] = b2[tid]; b3s[tid] = b3[tid]; }
    int j = tid & 63, g = tid >> 6;
    int n0 = blockIdx.x * 64;
    for (int it = 0; it < 16; ++it) {
        int node = n0 + it * 4 + g;
        __syncthreads();
        xs[g][j] = (node < N) ? g_agg[(long)node * 64 + j] : 0.f;
        __syncthreads();
        float acc = b2s[j];
#pragma unroll
        for (int k = 0; k < 64; k += 4) {
            float4 xv = *(const float4*)&xs[g][k];
            acc += xv.x * W2s[(k + 0) * 65 + j];
            acc += xv.y * W2s[(k + 1) * 65 + j];
            acc += xv.z * W2s[(k + 2) * 65 + j];
            acc += xv.w * W2s[(k + 3) * 65 + j];
        }
        ts[g][j] = sspf(acc);
        __syncthreads();
        float acc2 = b3s[j];
#pragma unroll
        for (int k = 0; k < 64; k += 4) {
            float4 tv = *(const float4*)&ts[g][k];
            acc2 += tv.x * W3s[(k + 0) * 65 + j];
            acc2 += tv.y * W3s[(k + 1) * 65 + j];
            acc2 += tv.z * W3s[(k + 2) * 65 + j];
            acc2 += tv.w * W3s[(k + 3) * 65 + j];
        }
        if (node < N) out[(long)node * 64 + j] = acc2 + x0[(long)node * 64 + j];
    }
}

// ---------------------------------------------------------------------------
// edge kernel: persistent, TMA box loads for rbf, resident fragment weights
// smem (floats):
#define OFF_A   0        // 2 bufs x 256 rows x 32 cols = 16384 (64KB)
#define OFF_FW1 16384    // 10240 float2 = 20480 floats (80KB)
#define OFF_FW2 36864    // 2048 float2 = 4096 floats (16KB)
#define OFF_C   40960    // 256 x 64 = 16384 (64KB)
#define OFF_B1  57344
#define OFF_B2  57408
#define OFF_MB  57472    // 2 mbarriers
#define SMEM_FLOATS 57476
// C swizzled word index
#define CSW(r, c) ((r) * 64 + ((c) ^ (((r) & 7) << 2)))

__global__ void __launch_bounds__(512, 1)
edge_kernel(const __grid_constant__ CUtensorMap tmap, const void* __restrict__ ei,
            const float* __restrict__ dist, const float* __restrict__ cutoff,
            const float* __restrict__ fb1, const float* __restrict__ fb2,
            int E, int NT, int GRIDSZ) {
    extern __shared__ __align__(1024) float sm[];
    uint32_t sbase = (uint32_t)__cvta_generic_to_shared(sm);
    int tid = threadIdx.x, lane = tid & 31, warp = tid >> 5;
    int t4 = lane & 3, g4 = lane >> 2, rw = warp * 16;
    const float2* FW1 = (const float2*)(sm + OFF_FW1);
    const float2* FW2 = (const float2*)(sm + OFF_FW2);
    uint32_t mb0 = sbase + OFF_MB * 4, mb1 = mb0 + 8;

    // stage weights (once per CTA) + biases, init mbarriers
    for (int i = tid; i < 5120; i += 512)
        cp16(sbase + (OFF_FW1 + i * 4) * 4, (const char*)g_fw1frag + i * 16, 16);
    for (int i = tid; i < 1024; i += 512)
        cp16(sbase + (OFF_FW2 + i * 4) * 4, (const char*)g_fw2frag + i * 16, 16);
    cp_commit();
    if (tid < 64) { sm[OFF_B1 + tid] = fb1[tid]; sm[OFF_B2 + tid] = fb2[tid]; }
    if (tid == 0) { mbar_init(mb0, 1); mbar_init(mb1, 1); }
    cp_wait0();
    asm volatile("fence.proxy.async.shared::cta;" ::: "memory");
    __syncthreads();

    auto issue = [&](long t, int c, int b) {
        if (tid != 0 || t >= (long)NT) return;
        uint32_t mb = b ? mb1 : mb0;
        mbar_expect(mb, 32768u);
        tma2d(sbase + (OFF_A + b * 8192) * 4, (const void*)&tmap,
              c * 32, (int)(t * TILE), mb);
    };

    long tile = blockIdx.x;
    issue(tile, 0, 0);
    issue(tile, 1, 1);
    int ph0 = 0, ph1 = 0;

    for (; tile < (long)NT; tile += GRIDSZ) {
        long e0 = tile * TILE;
        float acc[8][4];
#pragma unroll
        for (int t = 0; t < 8; ++t)
#pragma unroll
            for (int j = 0; j < 4; ++j) acc[t][j] = 0.f;

#pragma unroll 1
        for (int c = 0; c < 10; ++c) {
            int b = c & 1;
            if (b) { mbar_wait(mb1, ph1); ph1 ^= 1; }
            else   { mbar_wait(mb0, ph0); ph0 ^= 1; }
            const float* A = sm + OFF_A + b * 8192;
            int r0 = rw + g4, r1 = r0 + 8;
            int sw = g4 << 2;  // (r&7)<<2 is same for r0, r1
#pragma unroll
            for (int s = 0; s < 4; ++s) {
                int w0 = 8 * s + t4;
                uint32_t a0 = cvt_tf32(A[r0 * 32 + (w0 ^ sw)]);
                uint32_t a1 = cvt_tf32(A[r1 * 32 + (w0 ^ sw)]);
                uint32_t a2 = cvt_tf32(A[r0 * 32 + ((w0 + 4) ^ sw)]);
                uint32_t a3 = cvt_tf32(A[r1 * 32 + ((w0 + 4) ^ sw)]);
#pragma unroll
                for (int t = 0; t < 8; ++t) {
                    float2 bb = FW1[((c * 4 + s) * 8 + t) * 32 + lane];
                    mma_tf32(acc[t], a0, a1, a2, a3,
                             __float_as_uint(bb.x), __float_as_uint(bb.y));
                }
            }
            __syncthreads();
            if (c < 8) issue(tile, c + 2, b);
            else issue(tile + GRIDSZ, c - 8, b);
        }

        // bias + ssp -> C (own-warp rows only)
#pragma unroll
        for (int t = 0; t < 8; ++t) {
            int cb = 8 * t + 2 * t4;
            float b0v = sm[OFF_B1 + cb], b1v = sm[OFF_B1 + cb + 1];
            *(float2*)&sm[OFF_C + CSW(rw + g4, cb)] =
                make_float2(sspf(acc[t][0] + b0v), sspf(acc[t][1] + b1v));
            *(float2*)&sm[OFF_C + CSW(rw + g4 + 8, cb)] =
                make_float2(sspf(acc[t][2] + b0v), sspf(acc[t][3] + b1v));
        }
        __syncwarp();

        // GEMM2: C[256,64] @ fw2
        float acc2[8][4];
#pragma unroll
        for (int t = 0; t < 8; ++t)
#pragma unroll
            for (int j = 0; j < 4; ++j) acc2[t][j] = 0.f;
#pragma unroll
        for (int s = 0; s < 8; ++s) {
            int col = 8 * s + t4;
            uint32_t a0 = cvt_tf32(sm[OFF_C + CSW(rw + g4, col)]);
            uint32_t a1 = cvt_tf32(sm[OFF_C + CSW(rw + g4 + 8, col)]);
            uint32_t a2 = cvt_tf32(sm[OFF_C + CSW(rw + g4, col + 4)]);
            uint32_t a3 = cvt_tf32(sm[OFF_C + CSW(rw + g4 + 8, col + 4)]);
#pragma unroll
            for (int t = 0; t < 8; ++t) {
                float2 bb = FW2[(s * 8 + t) * 32 + lane];
                mma_tf32(acc2[t], a0, a1, a2, a3,
                         __float_as_uint(bb.x), __float_as_uint(bb.y));
            }
        }
        __syncwarp();
#pragma unroll
        for (int t = 0; t < 8; ++t) {
            int cb = 8 * t + 2 * t4;
            float b0v = sm[OFF_B2 + cb], b1v = sm[OFF_B2 + cb + 1];
            *(float2*)&sm[OFF_C + CSW(rw + g4, cb)] =
                make_float2(sspf(acc2[t][0] + b0v), sspf(acc2[t][1] + b1v));
            *(float2*)&sm[OFF_C + CSW(rw + g4 + 8, cb)] =
                make_float2(sspf(acc2[t][2] + b0v), sspf(acc2[t][3] + b1v));
        }
        __syncthreads();

        // epilogue: gather h[src], scatter atomics into agg[dst]
        int el = tid >> 1, half = tid & 1;
        long e = e0 + el;
        if (e < (long)E) {
            long long dstn, srcn;
            if (g_is64) {
                const long long* p = (const long long*)ei;
                dstn = p[e]; srcn = p[(long)E + e];
            } else {
                const int* p = (const int*)ei;
                dstn = p[e]; srcn = p[(long)E + e];
            }
            dstn = dstn < 0 ? 0 : (dstn >= NMAX ? NMAX - 1 : dstn);
            srcn = srcn < 0 ? 0 : (srcn >= NMAX ? NMAX - 1 : srcn);
            float f = 1.f + __cosf(3.14159265f * dist[e] / *cutoff);
            const float* hrow = g_h + (long)srcn * 64 + half * 32;
            float* arow = g_agg + (long)dstn * 64 + half * 32;
#pragma unroll
            for (int j = 0; j < 8; ++j) {
                float4 w = *(const float4*)&sm[OFF_C + CSW(el, half * 32 + 4 * j)];
                float4 h4 = *(const float4*)(hrow + 4 * j);
                atomicAdd((float4*)(arow + 4 * j),
                          make_float4(w.x * h4.x * f, w.y * h4.y * f,
                                      w.z * h4.z * f, w.w * h4.w * f));
            }
        }
        __syncthreads();
    }
}

// ---------------------------------------------------------------------------
typedef CUresult (*PFN_tmencode)(
    CUtensorMap*, CUtensorMapDataType, cuuint32_t, void*,
    const cuuint64_t*, const cuuint64_t*, const cuuint32_t*, const cuuint32_t*,
    CUtensorMapInterleave, CUtensorMapSwizzle, CUtensorMapL2promotion,
    CUtensorMapFloatOOBfill);

extern "C" void kernel_launch(void* const* d_in, const int* in_sizes, int n_in,
                              void* d_out, int out_size) {
    const void* ei       = d_in[0];
    const float* x       = (const float*)d_in[1];
    const float* rbf     = (const float*)d_in[2];
    const float* dist    = (const float*)d_in[3];
    const float* cutoff  = (const float*)d_in[4];
    const float* fw1     = (const float*)d_in[5];
    const float* fb1     = (const float*)d_in[6];
    const float* fw2     = (const float*)d_in[7];
    const float* fb2     = (const float*)d_in[8];
    const float* l1w     = (const float*)d_in[9];
    const float* l1b     = (const float*)d_in[10];
    const float* l2w     = (const float*)d_in[11];
    const float* l2b     = (const float*)d_in[12];
    const float* l3w     = (const float*)d_in[13];
    const float* l3b     = (const float*)d_in[14];

    int E = in_sizes[0] / 2;
    int N = in_sizes[1] / 64;
    int NT = (E + TILE - 1) / TILE;

    static PFN_tmencode enc = nullptr;
    if (!enc) {
        cudaDriverEntryPointQueryResult st;
        cudaGetDriverEntryPointByVersion("cuTensorMapEncodeTiled", (void**)&enc,
                                         12000, cudaEnableDefault, &st);
    }
    alignas(64) CUtensorMap tmap;
    {
        cuuint64_t dims[2]    = {(cuuint64_t)RK, (cuuint64_t)E};
        cuuint64_t strides[1] = {(cuuint64_t)RK * 4};
        cuuint32_t box[2]     = {32, TILE};
        cuuint32_t estr[2]    = {1, 1};
        enc(&tmap, CU_TENSOR_MAP_DATA_TYPE_FLOAT32, 2, (void*)rbf,
            dims, strides, box, estr,
            CU_TENSOR_MAP_INTERLEAVE_NONE, CU_TENSOR_MAP_SWIZZLE_128B,
            CU_TENSOR_MAP_L2_PROMOTION_L2_128B, CU_TENSOR_MAP_FLOAT_OOB_FILL_NONE);
    }

    static int sms = 0;
    if (!sms) cudaDeviceGetAttribute(&sms, cudaDevAttrMultiProcessorCount, 0);
    int grid = sms > 0 ? sms : 148;

    cudaFuncSetAttribute(edge_kernel, cudaFuncAttributeMaxDynamicSharedMemorySize,
                         SMEM_FLOATS * 4);

    detect_idx_kernel<<<1, 32>>>((const int*)ei);
    prep_frag_kernel<<<(10 * 4 * 8 * 32 + 255) / 256, 256>>>(fw1, fw2);
    zero_agg_kernel<<<(N * 16 + 255) / 256, 256>>>(N * 16);
    node_pre_kernel<<<(N + 63) / 64, 256>>>(x, l1w, l1b, N);
    edge_kernel<<<grid, 512, SMEM_FLOATS * 4>>>(tmap, ei, dist, cutoff,
                                                fb1, fb2, E, NT, grid);
    node_post_kernel<<<(N + 63) / 64, 256>>>(x, l2w, l2b, l3w, l3b, (float*)d_out, N);
}

// round 6
// speedup vs baseline: 2.5312x; 1.1736x over previous
#include <cuda_runtime.h>
#include <cuda.h>
#include <cstdint>

#define NMAX 50000
#define RK 300
#define TILE 256

__device__ float g_h[NMAX * 64];
__device__ float g_agg[NMAX * 64];
__device__ float2 g_fw1frag[10 * 4 * 8 * 32];  // [c][s][t][lane] -> (b0,b1)
__device__ float2 g_fw2frag[8 * 8 * 32];       // [s][t][lane]
__device__ int g_is64;

__device__ __forceinline__ float sspf(float x) {
    float t = __expf(-fabsf(x));
    return fmaxf(x, 0.f) + __logf(1.f + t) - 0.69314718055994531f;
}
__device__ __forceinline__ uint32_t cvt_tf32(float x) {
    uint32_t r; asm("cvt.rna.tf32.f32 %0, %1;" : "=r"(r) : "f"(x)); return r;
}
__device__ __forceinline__ float tf32r(float x) { return __uint_as_float(cvt_tf32(x)); }

__device__ __forceinline__ void mma_tf32(float d[4], uint32_t a0, uint32_t a1,
                                         uint32_t a2, uint32_t a3,
                                         uint32_t b0, uint32_t b1) {
    asm volatile(
        "mma.sync.aligned.m16n8k8.row.col.f32.tf32.tf32.f32 "
        "{%0,%1,%2,%3}, {%4,%5,%6,%7}, {%8,%9}, {%0,%1,%2,%3};"
        : "+f"(d[0]), "+f"(d[1]), "+f"(d[2]), "+f"(d[3])
        : "r"(a0), "r"(a1), "r"(a2), "r"(a3), "r"(b0), "r"(b1));
}
__device__ __forceinline__ void cp16(uint32_t saddr, const void* g, int sz) {
    asm volatile("cp.async.cg.shared.global [%0], [%1], 16, %2;"
                 :: "r"(saddr), "l"(g), "r"(sz));
}
__device__ __forceinline__ void cp_commit() { asm volatile("cp.async.commit_group;"); }
__device__ __forceinline__ void cp_wait0()  { asm volatile("cp.async.wait_group 0;"); }

__device__ __forceinline__ void tma2d(uint32_t dst, const void* map, int x, int y,
                                      uint32_t mbar) {
    asm volatile(
        "cp.async.bulk.tensor.2d.shared::cta.global.tile.mbarrier::complete_tx::bytes "
        "[%0], [%1, {%2, %3}], [%4];"
        :: "r"(dst), "l"(map), "r"(x), "r"(y), "r"(mbar) : "memory");
}
__device__ __forceinline__ void mbar_init(uint32_t a, uint32_t cnt) {
    asm volatile("mbarrier.init.shared.b64 [%0], %1;" :: "r"(a), "r"(cnt) : "memory");
}
__device__ __forceinline__ void mbar_expect(uint32_t a, uint32_t tx) {
    asm volatile("mbarrier.arrive.expect_tx.shared.b64 _, [%0], %1;"
                 :: "r"(a), "r"(tx) : "memory");
}
__device__ __forceinline__ void mbar_wait(uint32_t a, uint32_t ph) {
    uint32_t done = 0;
    do {
        asm volatile(
            "{\n\t.reg .pred p;\n\t"
            "mbarrier.try_wait.parity.acquire.cta.shared::cta.b64 p, [%1], %2, 0x989680;\n\t"
            "selp.b32 %0, 1, 0, p;\n\t}"
            : "=r"(done) : "r"(a), "r"(ph) : "memory");
    } while (!done);
}

__global__ void detect_idx_kernel(const int* __restrict__ ei32) {
    if (threadIdx.x == 0 && blockIdx.x == 0) {
        int ornz = 0;
#pragma unroll
        for (int i = 0; i < 64; ++i) ornz |= ei32[2 * i + 1];
        g_is64 = (ornz == 0) ? 1 : 0;
    }
}

// fragment-major tf32 weights. fw1: k = c*32 + 8s + t4 (+4 for b1), n = 8t + g4
__global__ void prep_frag_kernel(const float* __restrict__ fw1,
                                 const float* __restrict__ fw2) {
    int i = blockIdx.x * blockDim.x + threadIdx.x;
    if (i < 10 * 4 * 8 * 32) {
        int lane = i & 31, t = (i >> 5) & 7, s = (i >> 8) & 3, c = i >> 10;
        int t4 = lane & 3, g4 = lane >> 2;
        int k = c * 32 + 8 * s + t4, n = 8 * t + g4;
        float b0 = (k < RK) ? tf32r(fw1[k * 64 + n]) : 0.f;
        float b1 = (k + 4 < RK) ? tf32r(fw1[(k + 4) * 64 + n]) : 0.f;
        g_fw1frag[i] = make_float2(b0, b1);
    }
    if (i < 8 * 8 * 32) {
        int lane = i & 31, t = (i >> 5) & 7, s = i >> 8;
        int t4 = lane & 3, g4 = lane >> 2;
        int k = 8 * s + t4, n = 8 * t + g4;
        g_fw2frag[i] = make_float2(tf32r(fw2[k * 64 + n]), tf32r(fw2[(k + 4) * 64 + n]));
    }
}

// ---------------------------------------------------------------------------
// node_pre: h = x @ l1w + l1b, and zero g_agg. 128 nodes/block, 2 barriers.
// ---------------------------------------------------------------------------
__global__ void __launch_bounds__(256)
node_pre_kernel(const float* __restrict__ x, const float* __restrict__ W,
                const float* __restrict__ b, int N) {
    __shared__ float xs[128 * 64];
    int tid = threadIdx.x;
    int j = tid & 63, q = tid >> 6;
    long n0 = (long)blockIdx.x * 128;
    uint32_t sb = (uint32_t)__cvta_generic_to_shared(xs);
    for (int i = tid; i < 2048; i += 256) {
        long node = n0 + (i >> 4);
        cp16(sb + i * 16, x + node * 64 + (i & 15) * 4, node < N ? 16 : 0);
    }
    cp_commit();
    float Wc[64];
#pragma unroll
    for (int k = 0; k < 64; ++k) Wc[k] = W[k * 64 + j];
    float bj = b[j];
    cp_wait0();
    __syncthreads();
#pragma unroll 4
    for (int nn = 0; nn < 32; ++nn) {
        int r = nn * 4 + q;
        long node = n0 + r;
        float acc = bj;
        const float* xr = xs + r * 64;
#pragma unroll
        for (int k = 0; k < 64; k += 4) {
            float4 xv = *(const float4*)(xr + k);
            acc += xv.x * Wc[k] + xv.y * Wc[k + 1] + xv.z * Wc[k + 2] + xv.w * Wc[k + 3];
        }
        if (node < N) {
            g_h[node * 64 + j] = acc;
            g_agg[node * 64 + j] = 0.f;
        }
    }
}

// ---------------------------------------------------------------------------
// node_post: out = ssp(agg @ l2w + l2b) @ l3w + l3b + x0. 128 nodes/block.
// ---------------------------------------------------------------------------
__global__ void __launch_bounds__(256)
node_post_kernel(const float* __restrict__ x0, const float* __restrict__ W2,
                 const float* __restrict__ b2, const float* __restrict__ W3,
                 const float* __restrict__ b3, float* __restrict__ out, int N) {
    extern __shared__ float smp[];
    float* xs = smp;            // 128*64
    float* ts = smp + 8192;     // 128*64
    int tid = threadIdx.x;
    int j = tid & 63, q = tid >> 6;
    long n0 = (long)blockIdx.x * 128;
    uint32_t sb = (uint32_t)__cvta_generic_to_shared(xs);
    for (int i = tid; i < 2048; i += 256) {
        long node = n0 + (i >> 4);
        cp16(sb + i * 16, g_agg + node * 64 + (i & 15) * 4, node < N ? 16 : 0);
    }
    cp_commit();
    float W2c[64], W3c[64];
#pragma unroll
    for (int k = 0; k < 64; ++k) { W2c[k] = W2[k * 64 + j]; W3c[k] = W3[k * 64 + j]; }
    float b2j = b2[j], b3j = b3[j];
    cp_wait0();
    __syncthreads();
#pragma unroll 4
    for (int nn = 0; nn < 32; ++nn) {
        int r = nn * 4 + q;
        float acc = b2j;
        const float* xr = xs + r * 64;
#pragma unroll
        for (int k = 0; k < 64; k += 4) {
            float4 xv = *(const float4*)(xr + k);
            acc += xv.x * W2c[k] + xv.y * W2c[k + 1] + xv.z * W2c[k + 2] + xv.w * W2c[k + 3];
        }
        ts[r * 64 + j] = sspf(acc);
    }
    __syncthreads();
#pragma unroll 4
    for (int nn = 0; nn < 32; ++nn) {
        int r = nn * 4 + q;
        long node = n0 + r;
        float acc = b3j;
        const float* tr = ts + r * 64;
#pragma unroll
        for (int k = 0; k < 64; k += 4) {
            float4 tv = *(const float4*)(tr + k);
            acc += tv.x * W3c[k] + tv.y * W3c[k + 1] + tv.z * W3c[k + 2] + tv.w * W3c[k + 3];
        }
        if (node < N) out[node * 64 + j] = acc + x0[node * 64 + j];
    }
}

// ---------------------------------------------------------------------------
// edge kernel: persistent, TMA box loads for rbf, resident fragment weights,
// shuffle-based GEMM1->GEMM2 handoff (no smem round-trip).
// ---------------------------------------------------------------------------
#define OFF_A   0        // 2 bufs x 256 rows x 32 cols = 16384 (64KB)
#define OFF_FW1 16384    // 10240 float2 = 20480 floats (80KB)
#define OFF_FW2 36864    // 2048 float2 = 4096 floats (16KB)
#define OFF_C   40960    // 256 x 64 = 16384 (64KB)
#define OFF_B1  57344
#define OFF_B2  57408
#define OFF_MB  57472    // 2 mbarriers
#define SMEM_FLOATS 57476
#define CSW(r, c) ((r) * 64 + ((c) ^ (((r) & 7) << 2)))

__global__ void __launch_bounds__(512, 1)
edge_kernel(const __grid_constant__ CUtensorMap tmap, const void* __restrict__ ei,
            const float* __restrict__ dist, const float* __restrict__ cutoff,
            const float* __restrict__ fb1, const float* __restrict__ fb2,
            int E, int NT, int GRIDSZ) {
    extern __shared__ __align__(1024) float sm[];
    uint32_t sbase = (uint32_t)__cvta_generic_to_shared(sm);
    int tid = threadIdx.x, lane = tid & 31, warp = tid >> 5;
    int t4 = lane & 3, g4 = lane >> 2, rw = warp * 16;
    const float2* FW1 = (const float2*)(sm + OFF_FW1);
    const float2* FW2 = (const float2*)(sm + OFF_FW2);
    uint32_t mb0 = sbase + OFF_MB * 4, mb1 = mb0 + 8;

    for (int i = tid; i < 5120; i += 512)
        cp16(sbase + (OFF_FW1 + i * 4) * 4, (const char*)g_fw1frag + i * 16, 16);
    for (int i = tid; i < 1024; i += 512)
        cp16(sbase + (OFF_FW2 + i * 4) * 4, (const char*)g_fw2frag + i * 16, 16);
    cp_commit();
    if (tid < 64) { sm[OFF_B1 + tid] = fb1[tid]; sm[OFF_B2 + tid] = fb2[tid]; }
    if (tid == 0) { mbar_init(mb0, 1); mbar_init(mb1, 1); }
    cp_wait0();
    asm volatile("fence.proxy.async.shared::cta;" ::: "memory");
    __syncthreads();

    int is64 = g_is64;
    float cf = *cutoff;
    float picf = 3.14159265f / cf;

    auto issue = [&](long t, int c, int b) {
        if (tid != 0 || t >= (long)NT) return;
        uint32_t mb = b ? mb1 : mb0;
        mbar_expect(mb, 32768u);
        tma2d(sbase + (OFF_A + b * 8192) * 4, (const void*)&tmap,
              c * 32, (int)(t * TILE), mb);
    };

    long tile = blockIdx.x;
    issue(tile, 0, 0);
    issue(tile, 1, 1);
    int ph0 = 0, ph1 = 0;

    int el = tid >> 1, half = tid & 1;
    int u = t4 >> 1, p = t4 & 1;
    int l1 = 4 * g4 + u, l2 = l1 + 2;

    for (; tile < (long)NT; tile += GRIDSZ) {
        long e0 = tile * TILE;

        // preload epilogue indices/dist early (hide L2 latency behind GEMM1)
        long e = e0 + el;
        long long dstn = 0, srcn = 0;
        float f = 0.f;
        if (e < (long)E) {
            if (is64) {
                const long long* pp = (const long long*)ei;
                dstn = pp[e]; srcn = pp[(long)E + e];
            } else {
                const int* pp = (const int*)ei;
                dstn = pp[e]; srcn = pp[(long)E + e];
            }
            dstn = dstn < 0 ? 0 : (dstn >= NMAX ? NMAX - 1 : dstn);
            srcn = srcn < 0 ? 0 : (srcn >= NMAX ? NMAX - 1 : srcn);
            f = 1.f + __cosf(picf * dist[e]);
        }

        float acc[8][4];
#pragma unroll
        for (int t = 0; t < 8; ++t)
#pragma unroll
            for (int jj = 0; jj < 4; ++jj) acc[t][jj] = 0.f;

#pragma unroll 1
        for (int c = 0; c < 10; ++c) {
            int b = c & 1;
            if (b) { mbar_wait(mb1, ph1); ph1 ^= 1; }
            else   { mbar_wait(mb0, ph0); ph0 ^= 1; }
            const float* A = sm + OFF_A + b * 8192;
            int r0 = rw + g4, r1 = r0 + 8;
            int sw = g4 << 2;
#pragma unroll
            for (int s = 0; s < 4; ++s) {
                int w0 = 8 * s + t4;
                uint32_t a0 = cvt_tf32(A[r0 * 32 + (w0 ^ sw)]);
                uint32_t a1 = cvt_tf32(A[r1 * 32 + (w0 ^ sw)]);
                uint32_t a2 = cvt_tf32(A[r0 * 32 + ((w0 + 4) ^ sw)]);
                uint32_t a3 = cvt_tf32(A[r1 * 32 + ((w0 + 4) ^ sw)]);
#pragma unroll
                for (int t = 0; t < 8; ++t) {
                    float2 bb = FW1[((c * 4 + s) * 8 + t) * 32 + lane];
                    mma_tf32(acc[t], a0, a1, a2, a3,
                             __float_as_uint(bb.x), __float_as_uint(bb.y));
                }
            }
            __syncthreads();
            if (c < 8) issue(tile, c + 2, b);
            else issue(tile + GRIDSZ, c - 8, b);
        }

        // bias + ssp in-place on acc
#pragma unroll
        for (int t = 0; t < 8; ++t) {
            int cb = 8 * t + 2 * t4;
            float b0v = sm[OFF_B1 + cb], b1v = sm[OFF_B1 + cb + 1];
            acc[t][0] = sspf(acc[t][0] + b0v);
            acc[t][1] = sspf(acc[t][1] + b1v);
            acc[t][2] = sspf(acc[t][2] + b0v);
            acc[t][3] = sspf(acc[t][3] + b1v);
        }

        // GEMM2 with A-fragments gathered via warp shuffles (no smem round-trip)
        float acc2[8][4];
#pragma unroll
        for (int t = 0; t < 8; ++t)
#pragma unroll
            for (int jj = 0; jj < 4; ++jj) acc2[t][jj] = 0.f;
#pragma unroll
        for (int s = 0; s < 8; ++s) {
            float v00 = __shfl_sync(0xffffffffu, acc[s][0], l1);
            float v01 = __shfl_sync(0xffffffffu, acc[s][1], l1);
            float v10 = __shfl_sync(0xffffffffu, acc[s][2], l1);
            float v11 = __shfl_sync(0xffffffffu, acc[s][3], l1);
            float w00 = __shfl_sync(0xffffffffu, acc[s][0], l2);
            float w01 = __shfl_sync(0xffffffffu, acc[s][1], l2);
            float w10 = __shfl_sync(0xffffffffu, acc[s][2], l2);
            float w11 = __shfl_sync(0xffffffffu, acc[s][3], l2);
            uint32_t a0 = cvt_tf32(p ? v01 : v00);
            uint32_t a1 = cvt_tf32(p ? v11 : v10);
            uint32_t a2 = cvt_tf32(p ? w01 : w00);
            uint32_t a3 = cvt_tf32(p ? w11 : w10);
#pragma unroll
            for (int t = 0; t < 8; ++t) {
                float2 bb = FW2[(s * 8 + t) * 32 + lane];
                mma_tf32(acc2[t], a0, a1, a2, a3,
                         __float_as_uint(bb.x), __float_as_uint(bb.y));
            }
        }

        // bias + ssp -> C (for per-edge epilogue access)
#pragma unroll
        for (int t = 0; t < 8; ++t) {
            int cb = 8 * t + 2 * t4;
            float b0v = sm[OFF_B2 + cb], b1v = sm[OFF_B2 + cb + 1];
            *(float2*)&sm[OFF_C + CSW(rw + g4, cb)] =
                make_float2(sspf(acc2[t][0] + b0v), sspf(acc2[t][1] + b1v));
            *(float2*)&sm[OFF_C + CSW(rw + g4 + 8, cb)] =
                make_float2(sspf(acc2[t][2] + b0v), sspf(acc2[t][3] + b1v));
        }
        __syncthreads();

        // epilogue: gather h[src], scatter atomics into agg[dst]
        if (e < (long)E) {
            const float* hrow = g_h + (long)srcn * 64 + half * 32;
            float* arow = g_agg + (long)dstn * 64 + half * 32;
#pragma unroll
            for (int jj = 0; jj < 8; ++jj) {
                float4 w = *(const float4*)&sm[OFF_C + CSW(el, half * 32 + 4 * jj)];
                float4 h4 = *(const float4*)(hrow + 4 * jj);
                atomicAdd((float4*)(arow + 4 * jj),
                          make_float4(w.x * h4.x * f, w.y * h4.y * f,
                                      w.z * h4.z * f, w.w * h4.w * f));
            }
        }
        __syncthreads();
    }
}

// ---------------------------------------------------------------------------
typedef CUresult (*PFN_tmencode)(
    CUtensorMap*, CUtensorMapDataType, cuuint32_t, void*,
    const cuuint64_t*, const cuuint64_t*, const cuuint32_t*, const cuuint32_t*,
    CUtensorMapInterleave, CUtensorMapSwizzle, CUtensorMapL2promotion,
    CUtensorMapFloatOOBfill);

extern "C" void kernel_launch(void* const* d_in, const int* in_sizes, int n_in,
                              void* d_out, int out_size) {
    const void* ei       = d_in[0];
    const float* x       = (const float*)d_in[1];
    const float* rbf     = (const float*)d_in[2];
    const float* dist    = (const float*)d_in[3];
    const float* cutoff  = (const float*)d_in[4];
    const float* fw1     = (const float*)d_in[5];
    const float* fb1     = (const float*)d_in[6];
    const float* fw2     = (const float*)d_in[7];
    const float* fb2     = (const float*)d_in[8];
    const float* l1w     = (const float*)d_in[9];
    const float* l1b     = (const float*)d_in[10];
    const float* l2w     = (const float*)d_in[11];
    const float* l2b     = (const float*)d_in[12];
    const float* l3w     = (const float*)d_in[13];
    const float* l3b     = (const float*)d_in[14];

    int E = in_sizes[0] / 2;
    int N = in_sizes[1] / 64;
    int NT = (E + TILE - 1) / TILE;
    int NB = (N + 127) / 128;

    static PFN_tmencode enc = nullptr;
    if (!enc) {
        cudaDriverEntryPointQueryResult st;
        cudaGetDriverEntryPointByVersion("cuTensorMapEncodeTiled", (void**)&enc,
                                         12000, cudaEnableDefault, &st);
    }
    alignas(64) CUtensorMap tmap;
    {
        cuuint64_t dims[2]    = {(cuuint64_t)RK, (cuuint64_t)E};
        cuuint64_t strides[1] = {(cuuint64_t)RK * 4};
        cuuint32_t box[2]     = {32, TILE};
        cuuint32_t estr[2]    = {1, 1};
        enc(&tmap, CU_TENSOR_MAP_DATA_TYPE_FLOAT32, 2, (void*)rbf,
            dims, strides, box, estr,
            CU_TENSOR_MAP_INTERLEAVE_NONE, CU_TENSOR_MAP_SWIZZLE_128B,
            CU_TENSOR_MAP_L2_PROMOTION_L2_128B, CU_TENSOR_MAP_FLOAT_OOB_FILL_NONE);
    }

    static int sms = 0;
    if (!sms) cudaDeviceGetAttribute(&sms, cudaDevAttrMultiProcessorCount, 0);
    int grid = sms > 0 ? sms : 148;

    cudaFuncSetAttribute(edge_kernel, cudaFuncAttributeMaxDynamicSharedMemorySize,
                         SMEM_FLOATS * 4);
    cudaFuncSetAttribute(node_post_kernel, cudaFuncAttributeMaxDynamicSharedMemorySize,
                         65536);

    detect_idx_kernel<<<1, 32>>>((const int*)ei);
    prep_frag_kernel<<<(10 * 4 * 8 * 32 + 255) / 256, 256>>>(fw1, fw2);
    node_pre_kernel<<<NB, 256>>>(x, l1w, l1b, N);
    edge_kernel<<<grid, 512, SMEM_FLOATS * 4>>>(tmap, ei, dist, cutoff,
                                                fb1, fb2, E, NT, grid);
    node_post_kernel<<<NB, 256, 65536>>>(x, l2w, l2b, l3w, l3b, (float*)d_out, N);
}